// round 11
// baseline (speedup 1.0000x reference)
#include <cuda_runtime.h>
#include <math.h>
#include <stdio.h>

// Problem constants (confirmed by round-9 diagnostics)
#define NLON  720
#define MMAXC 361
#define LMAXC 360
#define NLATC 361
#define BCC   256
#define ROWS1 (BCC * NLATC)   // 92416 = 722 * 128

// Scratch: cos DFT matrix + Re(xf) in [m][row] layout (133 MB)
__device__ float g_fc[NLATC * MMAXC];            // [n][m] cos matrix * 2pi/720
__device__ float g_sre[(size_t)MMAXC * ROWS1];   // [m][row], row = bc*361 + k

// -------------------------------------------------------------------------
// Cosine DFT matrix, exact integer phase reduction (m*n) mod 720.
// -------------------------------------------------------------------------
__global__ void fmat_kernel() {
    const float scale = 0.008726646259971648f;  // 2*pi/720
    int idx = blockIdx.x * blockDim.x + threadIdx.x;
    if (idx < NLATC * MMAXC) {
        int n = idx / MMAXC, m = idx % MMAXC;
        int ph = (n * m) % NLON;
        g_fc[idx] = scale * cosf(scale * (float)ph);
    }
}

// -------------------------------------------------------------------------
// Stage 1: folded cosine DFT as GEMM.
//   C[row][m] = sum_{n=0..360} s[n] * fc[n][m],
//   s[n] = x[row][n] + (1<=n<=359 ? x[row][720-n] : 0)
// Tiles: 128 rows x 128 m, BK=16, 256 threads, 8x8 per thread.
// Output: g_sre[m * ROWS1 + row].
// -------------------------------------------------------------------------
__global__ __launch_bounds__(256) void s1_gemm(const float* __restrict__ x)
{
    __shared__ float As[128 * 17];
    __shared__ float Bs[128 * 17];

    const int tid = threadIdx.x;
    const int tx = tid & 15, ty = tid >> 4;
    const int row0 = blockIdx.y * 128;
    const int m0   = blockIdx.x * 128;

    float acc[8][8];
#pragma unroll
    for (int i = 0; i < 8; i++)
#pragma unroll
        for (int j = 0; j < 8; j++) acc[i][j] = 0.0f;

    for (int k0 = 0; k0 < NLATC; k0 += 16) {
        // A tile (128 rows x 16 n) with symmetric fold
#pragma unroll
        for (int t = 0; t < 8; t++) {
            int i  = tid + t * 256;
            int rl = i >> 4, kk = i & 15;
            int kg = k0 + kk;
            const float* xr = x + (size_t)(row0 + rl) * NLON;
            float v = 0.0f;
            if (kg < NLATC) {
                v = xr[kg];
                if (kg >= 1 && kg <= 359) v += xr[NLON - kg];
            }
            As[rl * 17 + kk] = v;
        }
        // B tile (16 n x 128 m) -> [m][n]
#pragma unroll
        for (int t = 0; t < 8; t++) {
            int i  = tid + t * 256;
            int kk = i >> 7, ml = i & 127;
            int kg = k0 + kk, mg = m0 + ml;
            float v = 0.0f;
            if (kg < NLATC && mg < MMAXC) v = g_fc[kg * MMAXC + mg];
            Bs[ml * 17 + kk] = v;
        }
        __syncthreads();

#pragma unroll
        for (int kk = 0; kk < 16; kk++) {
            float a[8], b[8];
#pragma unroll
            for (int i = 0; i < 8; i++) a[i] = As[(tx + 16 * i) * 17 + kk];
#pragma unroll
            for (int j = 0; j < 8; j++) b[j] = Bs[(ty + 16 * j) * 17 + kk];
#pragma unroll
            for (int i = 0; i < 8; i++)
#pragma unroll
                for (int j = 0; j < 8; j++)
                    acc[i][j] = fmaf(a[i], b[j], acc[i][j]);
        }
        __syncthreads();
    }

#pragma unroll
    for (int j = 0; j < 8; j++) {
        int mg = m0 + ty + 16 * j;
        if (mg < MMAXC) {
            float* op = g_sre + (size_t)mg * ROWS1 + row0;
#pragma unroll
            for (int i = 0; i < 8; i++)
                op[tx + 16 * i] = acc[i][j];
        }
    }
}

// -------------------------------------------------------------------------
// Stage 2: per-m GEMM, REAL part only.
//   out[(r*360 + l)*361 + m] = sum_k g_sre[m][r*361+k] * W[(m*360+l)*361+k]
// Tiles: 128 r x 64 l, BK=16, 256 threads, 8x4 per thread.
// -------------------------------------------------------------------------
__global__ __launch_bounds__(256) void s2_gemm(const float* __restrict__ W,
                                               float* __restrict__ out,
                                               size_t out_n)
{
    __shared__ float Ar[128 * 17];
    __shared__ float Bs[64 * 17];

    const int tid = threadIdx.x;
    const int tx = tid & 15, ty = tid >> 4;
    const int m  = blockIdx.z;
    const int r0 = blockIdx.y * 128;
    const int l0 = blockIdx.x * 64;

    const float* __restrict__ Am = g_sre + (size_t)m * ROWS1;
    const float* __restrict__ Bw = W + (size_t)m * LMAXC * NLATC;

    float acc[8][4];
#pragma unroll
    for (int i = 0; i < 8; i++)
#pragma unroll
        for (int j = 0; j < 4; j++) acc[i][j] = 0.0f;

    for (int k0 = 0; k0 < NLATC; k0 += 16) {
        // A tile: 128 r x 16 k  (A[r][k] = g_sre[m][r*361 + k])
#pragma unroll
        for (int t = 0; t < 8; t++) {
            int i  = tid + t * 256;
            int rl = i >> 4, kk = i & 15;
            int kg = k0 + kk;
            int r  = r0 + rl;
            float v = 0.0f;
            if (kg < NLATC && r < BCC) v = Am[(size_t)r * NLATC + kg];
            Ar[rl * 17 + kk] = v;
        }
        // B tile: 64 l x 16 k
#pragma unroll
        for (int t = 0; t < 4; t++) {
            int i  = tid + t * 256;
            int ll = i >> 4, kk = i & 15;
            int kg = k0 + kk, lg = l0 + ll;
            float v = 0.0f;
            if (kg < NLATC && lg < LMAXC) v = Bw[(size_t)lg * NLATC + kg];
            Bs[ll * 17 + kk] = v;
        }
        __syncthreads();

#pragma unroll
        for (int kk = 0; kk < 16; kk++) {
            float a[8], b[4];
#pragma unroll
            for (int i = 0; i < 8; i++) a[i] = Ar[(tx + 16 * i) * 17 + kk];
#pragma unroll
            for (int j = 0; j < 4; j++) b[j] = Bs[(ty + 16 * j) * 17 + kk];
#pragma unroll
            for (int i = 0; i < 8; i++)
#pragma unroll
                for (int j = 0; j < 4; j++)
                    acc[i][j] = fmaf(a[i], b[j], acc[i][j]);
        }
        __syncthreads();
    }

    // Real-only stores: out holds out_size float32 elements (133 MB).
#pragma unroll
    for (int i = 0; i < 8; i++) {
        int r = r0 + tx + 16 * i;
        if (r < BCC) {
#pragma unroll
            for (int j = 0; j < 4; j++) {
                int l = l0 + ty + 16 * j;
                if (l < LMAXC) {
                    size_t idx = ((size_t)r * LMAXC + l) * MMAXC + m;
                    if (idx < out_n) out[idx] = acc[i][j];
                }
            }
        }
    }
}

// -------------------------------------------------------------------------
extern "C" void kernel_launch(void* const* d_in, const int* in_sizes, int n_in,
                              void* d_out, int out_size)
{
    cudaStreamCaptureStatus cs = cudaStreamCaptureStatusNone;
    cudaStreamIsCapturing(0, &cs);
    const int live = (cs == cudaStreamCaptureStatusNone);

#define CHK(tag) do { if (live) { \
    cudaError_t _e = cudaDeviceSynchronize(); \
    fprintf(stderr, "[diag] %-6s: %s\n", tag, cudaGetErrorName(_e)); } } while (0)

    // x = larger buffer; w = the other (both confirmed float32).
    int xi = 0, wi = (n_in >= 2) ? 1 : 0;
    if (n_in >= 2 && in_sizes[1] > in_sizes[0]) { xi = 1; wi = 0; }
    const float* x = (const float*)d_in[xi];
    const float* w = (const float*)d_in[wi];
    float* out = (float*)d_out;
    size_t out_n = (size_t)(long long)out_size;   // float32 elements

    fmat_kernel<<<(NLATC * MMAXC + 255) / 256, 256>>>();
    CHK("fmat");

    dim3 g1(3, 722);          // m-tiles(128)x3, row-tiles(128)x722
    s1_gemm<<<g1, 256>>>(x);
    CHK("s1");

    dim3 g2(6, 2, 361);       // l-tiles(64)x6, r-tiles(128)x2, m
    s2_gemm<<<g2, 256>>>(w, out, out_n);
    CHK("s2");
#undef CHK
}